// round 6
// baseline (speedup 1.0000x reference)
#include <cuda_runtime.h>
#include <math.h>

#define BATCH 512
#define HO 31
#define WO 31
#define HW 64
#define PLANE (HO * WO)

// Per-patch closed-form invariants of the quantum circuit:
//   S2 = sum p_i^2 ; D2 = signed sum of p_i^2, row sign (+,-,+,-),
//        col sign (+,-,-,+)  [CNOT-ring MSB-half membership]
//   dP = sum over pairs (i, i^12): rows 0<->3 and 1<->2, same column
// Outputs: per-kernel 3x2 linear map of (D2/S2, dP/S2); coefficients depend
// only on U3 of qubit 0 (wires-1..3 unitary cancels: real input, wire-0 obs).
// Each thread computes TWO vertically adjacent patches (rows 2p, 2p+1),
// which share 2 of their 4 input rows: 6 row-loads for 2 patches.

__global__ __launch_bounds__(256, 7) void qconv_kernel(const float* __restrict__ x,
                                                       const float* __restrict__ w,
                                                       float* __restrict__ out) {
    __shared__ float cf[24];
    const int tid = threadIdx.y * 32 + threadIdx.x;
    if (tid < 4) {
        const int k = tid;
        float th = w[k * 12 + 0], ph = w[k * 12 + 1], om = w[k * 12 + 2];
        float st, ct, spo, cpo, smp, cmp, sp, cp, som, com_;
        sincosf(th, &st, &ct);
        sincosf(ph, &sp, &cp);
        sincosf(ph + om, &spo, &cpo);
        sincosf(om - ph, &smp, &cmp);
        sincosf(om, &som, &com_);
        float c2 = 0.5f * (1.0f + ct);  // cos^2(theta/2)
        float s2 = 0.5f * (1.0f - ct);  // sin^2(theta/2)
        cf[k * 6 + 0] = st * cp;
        cf[k * 6 + 1] = 2.0f * (c2 * cpo - s2 * cmp);
        cf[k * 6 + 2] = st * sp;
        cf[k * 6 + 3] = 2.0f * (c2 * spo + s2 * smp);
        cf[k * 6 + 4] = ct;
        cf[k * 6 + 5] = -2.0f * st * com_;
    }
    __syncthreads();

    const int lane = threadIdx.x;
    if (lane >= WO) return;  // lane 31 idle (keeps all loads in-bounds)

    const int pair = blockIdx.x * 8 + threadIdx.y;  // 0..15 -> rows (2p, 2p+1)
    const int ho0 = pair * 2;
    const int ho1 = ho0 + 1;                        // ho1==31 invalid when pair==15
    const int b = blockIdx.y;

    // input rows 4*pair .. 4*pair+5 ; columns [2*lane .. 2*lane+3]
    const float* base = x + (size_t)b * (HW * HW) + (size_t)(4 * pair) * HW + lane * 2;

    float2 u0 = *reinterpret_cast<const float2*>(base);
    float2 v0 = *reinterpret_cast<const float2*>(base + 2);
    float2 u1 = *reinterpret_cast<const float2*>(base + HW);
    float2 v1 = *reinterpret_cast<const float2*>(base + HW + 2);
    float2 u2 = *reinterpret_cast<const float2*>(base + 2 * HW);
    float2 v2 = *reinterpret_cast<const float2*>(base + 2 * HW + 2);
    float2 u3 = *reinterpret_cast<const float2*>(base + 3 * HW);
    float2 v3 = *reinterpret_cast<const float2*>(base + 3 * HW + 2);

    const size_t obase0 = (size_t)b * 12 * PLANE + (size_t)ho0 * WO + lane;

    // ---- patch A: rows u0..u3 ----
    {
        float q0 = u0.x * u0.x + u0.y * u0.y + v0.x * v0.x + v0.y * v0.y;
        float q1 = u1.x * u1.x + u1.y * u1.y + v1.x * v1.x + v1.y * v1.y;
        float q2 = u2.x * u2.x + u2.y * u2.y + v2.x * v2.x + v2.y * v2.y;
        float q3 = u3.x * u3.x + u3.y * u3.y + v3.x * v3.x + v3.y * v3.y;
        float d0 = u0.x * u0.x - u0.y * u0.y - v0.x * v0.x + v0.y * v0.y;
        float d1 = u1.x * u1.x - u1.y * u1.y - v1.x * v1.x + v1.y * v1.y;
        float d2 = u2.x * u2.x - u2.y * u2.y - v2.x * v2.x + v2.y * v2.y;
        float d3 = u3.x * u3.x - u3.y * u3.y - v3.x * v3.x + v3.y * v3.y;
        float S = q0 + q1 + q2 + q3;
        float D = d0 - d1 + d2 - d3;   // row signs (+,-,+,-)
        float P = u0.x * u3.x + u0.y * u3.y + v0.x * v3.x + v0.y * v3.y
                + u1.x * u2.x + u1.y * u2.y + v1.x * v2.x + v1.y * v2.y;
        float inv = 1.0f / S;
        float Dl = D * inv, dd = P * inv;
#pragma unroll
        for (int k = 0; k < 4; ++k) {
            out[obase0 + (size_t)(3 * k + 0) * PLANE] = cf[k * 6 + 0] * Dl + cf[k * 6 + 1] * dd;
            out[obase0 + (size_t)(3 * k + 1) * PLANE] = cf[k * 6 + 2] * Dl + cf[k * 6 + 3] * dd;
            out[obase0 + (size_t)(3 * k + 2) * PLANE] = cf[k * 6 + 4] * Dl + cf[k * 6 + 5] * dd;
        }
    }

    // ---- patch B: rows u2,u3 + two new rows ----
    if (ho1 < HO) {
        float2 u4 = *reinterpret_cast<const float2*>(base + 4 * HW);
        float2 v4 = *reinterpret_cast<const float2*>(base + 4 * HW + 2);
        float2 u5 = *reinterpret_cast<const float2*>(base + 5 * HW);
        float2 v5 = *reinterpret_cast<const float2*>(base + 5 * HW + 2);

        float q0 = u2.x * u2.x + u2.y * u2.y + v2.x * v2.x + v2.y * v2.y;
        float q1 = u3.x * u3.x + u3.y * u3.y + v3.x * v3.x + v3.y * v3.y;
        float q2 = u4.x * u4.x + u4.y * u4.y + v4.x * v4.x + v4.y * v4.y;
        float q3 = u5.x * u5.x + u5.y * u5.y + v5.x * v5.x + v5.y * v5.y;
        float d0 = u2.x * u2.x - u2.y * u2.y - v2.x * v2.x + v2.y * v2.y;
        float d1 = u3.x * u3.x - u3.y * u3.y - v3.x * v3.x + v3.y * v3.y;
        float d2 = u4.x * u4.x - u4.y * u4.y - v4.x * v4.x + v4.y * v4.y;
        float d3 = u5.x * u5.x - u5.y * u5.y - v5.x * v5.x + v5.y * v5.y;
        float S = q0 + q1 + q2 + q3;
        float D = d0 - d1 + d2 - d3;   // row signs (+,-,+,-)
        float P = u2.x * u5.x + u2.y * u5.y + v2.x * v5.x + v2.y * v5.y
                + u3.x * u4.x + u3.y * u4.y + v3.x * v4.x + v3.y * v4.y;
        float inv = 1.0f / S;
        float Dl = D * inv, dd = P * inv;
        const size_t obase1 = obase0 + WO;
#pragma unroll
        for (int k = 0; k < 4; ++k) {
            out[obase1 + (size_t)(3 * k + 0) * PLANE] = cf[k * 6 + 0] * Dl + cf[k * 6 + 1] * dd;
            out[obase1 + (size_t)(3 * k + 1) * PLANE] = cf[k * 6 + 2] * Dl + cf[k * 6 + 3] * dd;
            out[obase1 + (size_t)(3 * k + 2) * PLANE] = cf[k * 6 + 4] * Dl + cf[k * 6 + 5] * dd;
        }
    }
}

extern "C" void kernel_launch(void* const* d_in, const int* in_sizes, int n_in,
                              void* d_out, int out_size) {
    const float* x = (const float*)d_in[0];
    const float* w = (const float*)d_in[1];
    if (n_in >= 2 && in_sizes[0] == 48) {  // robustness: weights listed first
        x = (const float*)d_in[1];
        w = (const float*)d_in[0];
    }
    float* out = (float*)d_out;

    dim3 blk(32, 8, 1);
    dim3 grd(2, BATCH, 1);  // 2 blocks x 512 batches; block covers 16 patch rows
    qconv_kernel<<<grd, blk>>>(x, w, out);
}

// round 7
// speedup vs baseline: 1.5860x; 1.5860x over previous
#include <cuda_runtime.h>
#include <math.h>

#define BATCH 512
#define HO 31
#define WO 31
#define HW 64
#define PLANE (HO * WO)

// Per-patch closed-form invariants of the quantum circuit:
//   S2 = sum p_i^2 ; D2 = signed sum of p_i^2 (row sign (+,-,+,-), col (+,-,-,+))
//   dP = sum over pairs (i, i^12): rows 0<->3 and 1<->2, same column
// Outputs: per-kernel 3x2 linear map of (D2/S2, dP/S2); coefficients depend
// only on U3 of qubit 0 (wires-1..3 unitary cancels: real input, wire-0 obs).
// Coefficients stored TRANSPOSED: cfT[j] = float4 of coef j for kernels 0..3,
// so the epilogue reads 6 LDS.128 instead of 24 LDS.32.

__global__ __launch_bounds__(128, 16) void qconv_kernel(const float* __restrict__ x,
                                                        const float* __restrict__ w,
                                                        float* __restrict__ out) {
    __shared__ float4 cfT[6];
    const int tid = threadIdx.y * 32 + threadIdx.x;
    if (tid < 4) {
        const int k = tid;
        float th = w[k * 12 + 0], ph = w[k * 12 + 1], om = w[k * 12 + 2];
        float st, ct, spo, cpo, smp, cmp, sp, cp, som, com_;
        sincosf(th, &st, &ct);
        sincosf(ph, &sp, &cp);
        sincosf(ph + om, &spo, &cpo);
        sincosf(om - ph, &smp, &cmp);
        sincosf(om, &som, &com_);
        float c2 = 0.5f * (1.0f + ct);  // cos^2(theta/2)
        float s2 = 0.5f * (1.0f - ct);  // sin^2(theta/2)
        float* cfs = reinterpret_cast<float*>(cfT);
        cfs[0 * 4 + k] = st * cp;                              // ex: coef of Dl
        cfs[1 * 4 + k] = 2.0f * (c2 * cpo - s2 * cmp);         // ex: coef of dd
        cfs[2 * 4 + k] = st * sp;                              // ey: coef of Dl
        cfs[3 * 4 + k] = 2.0f * (c2 * spo + s2 * smp);         // ey: coef of dd
        cfs[4 * 4 + k] = ct;                                   // ez: coef of Dl
        cfs[5 * 4 + k] = -2.0f * st * com_;                    // ez: coef of dd
    }
    __syncthreads();

    const int wo = threadIdx.x;                    // 0..31 (31 active)
    const int ho = blockIdx.y * 4 + threadIdx.y;   // blockDim.y = 4
    const int b  = blockIdx.z;
    if (wo >= WO || ho >= HO) return;

    const float* base = x + (size_t)b * (HW * HW) + (ho * 2) * HW + wo * 2;

    // patch p[kh*4 + kw] = x[b, 0, 2*ho+kh, 2*wo+kw]
    float p[16];
#pragma unroll
    for (int r = 0; r < 4; ++r) {
        float2 u = *reinterpret_cast<const float2*>(base + r * HW);
        float2 v = *reinterpret_cast<const float2*>(base + r * HW + 2);
        p[4 * r + 0] = u.x;
        p[4 * r + 1] = u.y;
        p[4 * r + 2] = v.x;
        p[4 * r + 3] = v.y;
    }

    const float sgn[16] = {1.f, -1.f, -1.f, 1.f, -1.f, 1.f, 1.f, -1.f,
                           1.f, -1.f, -1.f, 1.f, -1.f, 1.f, 1.f, -1.f};
    float S2 = 0.f, D2 = 0.f, dP = 0.f;
#pragma unroll
    for (int i = 0; i < 16; ++i) {
        float q = p[i] * p[i];
        S2 += q;
        D2 += sgn[i] * q;
    }
#pragma unroll
    for (int j = 0; j < 8; ++j) dP += p[j] * p[j ^ 12];

    float inv = 1.0f / S2;       // reference eps cancels exactly
    float Dl = D2 * inv;
    float dd = dP * inv;

    size_t obase = (size_t)b * 12 * PLANE + ho * WO + wo;
#pragma unroll
    for (int c = 0; c < 3; ++c) {                // component: ex / ey / ez
        float4 a = cfT[2 * c + 0];               // coef of Dl, kernels 0..3
        float4 bq = cfT[2 * c + 1];              // coef of dd, kernels 0..3
        out[obase + (size_t)(0 + c) * PLANE] = a.x * Dl + bq.x * dd;
        out[obase + (size_t)(3 + c) * PLANE] = a.y * Dl + bq.y * dd;
        out[obase + (size_t)(6 + c) * PLANE] = a.z * Dl + bq.z * dd;
        out[obase + (size_t)(9 + c) * PLANE] = a.w * Dl + bq.w * dd;
    }
}

extern "C" void kernel_launch(void* const* d_in, const int* in_sizes, int n_in,
                              void* d_out, int out_size) {
    const float* x = (const float*)d_in[0];
    const float* w = (const float*)d_in[1];
    if (n_in >= 2 && in_sizes[0] == 48) {  // robustness: weights listed first
        x = (const float*)d_in[1];
        w = (const float*)d_in[0];
    }
    float* out = (float*)d_out;

    dim3 blk(32, 4, 1);
    dim3 grd(1, 8, BATCH);   // 8 y-blocks x 4 rows cover HO=31; 4096 blocks
    qconv_kernel<<<grd, blk>>>(x, w, out);
}